// round 1
// baseline (speedup 1.0000x reference)
#include <cuda_runtime.h>
#include <cstdint>

#define BATCH 16
#define SEQ   2048
#define DIN   4096
#define DOUT  4096
#define RANK  64
#define SCALING (1.0f/64.0f)

// Scratch (device globals: allocation-free per harness rules)
__device__ float g_BxT[(size_t)BATCH * RANK * SEQ];     // 8 MB,  [b][r][n]
__device__ float g_At [(size_t)BATCH * RANK * DOUT];    // 16 MB, [b][r][o]
__device__ int   g_ids[BATCH];

// ---------------------------------------------------------------------------
// adapter_ids may arrive as int32 or int64 (jax x64 off canonicalizes to i32).
// int64-LE data viewed as int32 has all odd positions == 0 (ids < 64).
// For genuine random int32 ids, 8 odd positions all-zero has prob (1/64)^8.
// Only the first 64 bytes are read before deciding (safe for either dtype).
// ---------------------------------------------------------------------------
__global__ void norm_ids_kernel(const int* __restrict__ raw) {
    if (threadIdx.x == 0) {
        bool odd_zero = true;
        #pragma unroll
        for (int i = 1; i < 16; i += 2) odd_zero &= (raw[i] == 0);
        if (odd_zero) {
            const long long* r64 = (const long long*)raw;
            for (int i = 0; i < BATCH; i++) g_ids[i] = (int)r64[i];
        } else {
            for (int i = 0; i < BATCH; i++) g_ids[i] = raw[i];
        }
    }
}

// ---------------------------------------------------------------------------
// Transpose requested A slices: A[aid] is [DOUT][RANK] -> g_At[b] = [RANK][DOUT]
// Standard 32x32 smem tile transpose, coalesced both directions.
// grid: (DOUT/32, RANK/32, BATCH), block (32,8)
// ---------------------------------------------------------------------------
__global__ __launch_bounds__(256) void transposeA_kernel(const float* __restrict__ Am) {
    __shared__ float t[32][33];
    int b  = blockIdx.z;
    int aid = g_ids[b];
    int o0 = blockIdx.x * 32;
    int r0 = blockIdx.y * 32;
    const float* Ap = Am + (size_t)aid * DOUT * RANK;
    #pragma unroll
    for (int i = 0; i < 4; i++) {
        int o = o0 + threadIdx.y + i * 8;
        t[threadIdx.y + i * 8][threadIdx.x] = Ap[(size_t)o * RANK + r0 + threadIdx.x];
    }
    __syncthreads();
    float* Atp = g_At + (size_t)b * RANK * DOUT;
    #pragma unroll
    for (int i = 0; i < 4; i++) {
        int r = r0 + threadIdx.y + i * 8;
        Atp[(size_t)r * DOUT + o0 + threadIdx.x] = t[threadIdx.x][threadIdx.y + i * 8];
    }
}

// ---------------------------------------------------------------------------
// Stage 1: Bx[b,r,n] = sum_k x[b,n,k] * B[aid_b,r,k]
// Block: 128 n-rows x 64 r-cols output tile, K-tile = 32.
// 256 threads: (tx 0..15 -> 4 r-cols, ty 0..15 -> 8 n-rows), 32 acc each.
// Writes transposed layout [b][r][n] as 2x float4 per r (32B-sector aligned).
// grid: (SEQ/128, BATCH)
// ---------------------------------------------------------------------------
__global__ __launch_bounds__(256) void stage1_kernel(const float* __restrict__ x,
                                                     const float* __restrict__ Bm) {
    __shared__ float xs[32][132];  // [k][n], padded for float4 alignment
    __shared__ float bs[32][68];   // [k][r]
    int b  = blockIdx.y;
    int nt = blockIdx.x;
    int aid = g_ids[b];
    const float* xp = x  + ((size_t)b * SEQ + (size_t)nt * 128) * DIN;
    const float* Bp = Bm + (size_t)aid * RANK * DIN;
    int tid = threadIdx.x;
    int tx = tid & 15;
    int ty = tid >> 4;

    float acc[8][4];
    #pragma unroll
    for (int i = 0; i < 8; i++)
        #pragma unroll
        for (int j = 0; j < 4; j++) acc[i][j] = 0.f;

    for (int k0 = 0; k0 < DIN; k0 += 32) {
        // x tile: 128x32 floats = 1024 float4, 4 per thread, transposed store
        #pragma unroll
        for (int t = 0; t < 4; t++) {
            int idx = tid + t * 256;
            int row = idx >> 3;
            int cv  = idx & 7;
            float4 v = *(const float4*)(xp + (size_t)row * DIN + k0 + cv * 4);
            xs[cv*4+0][row] = v.x; xs[cv*4+1][row] = v.y;
            xs[cv*4+2][row] = v.z; xs[cv*4+3][row] = v.w;
        }
        // B tile: 64x32 floats = 512 float4, 2 per thread
        #pragma unroll
        for (int t = 0; t < 2; t++) {
            int idx = tid + t * 256;
            int row = idx >> 3;
            int cv  = idx & 7;
            float4 v = *(const float4*)(Bp + (size_t)row * DIN + k0 + cv * 4);
            bs[cv*4+0][row] = v.x; bs[cv*4+1][row] = v.y;
            bs[cv*4+2][row] = v.z; bs[cv*4+3][row] = v.w;
        }
        __syncthreads();
        #pragma unroll
        for (int kk = 0; kk < 32; kk++) {
            float4 a0 = *(const float4*)&xs[kk][ty * 8];
            float4 a1 = *(const float4*)&xs[kk][ty * 8 + 4];
            float4 bv = *(const float4*)&bs[kk][tx * 4];
            float a[8] = {a0.x, a0.y, a0.z, a0.w, a1.x, a1.y, a1.z, a1.w};
            float bb[4] = {bv.x, bv.y, bv.z, bv.w};
            #pragma unroll
            for (int i = 0; i < 8; i++)
                #pragma unroll
                for (int j = 0; j < 4; j++)
                    acc[i][j] = fmaf(a[i], bb[j], acc[i][j]);
        }
        __syncthreads();
    }

    // Write Bx transposed: g_BxT[b][r = tx*4+j][n = nt*128 + ty*8 + i]
    size_t base = ((size_t)b * RANK + (size_t)tx * 4) * SEQ + (size_t)nt * 128 + (size_t)ty * 8;
    #pragma unroll
    for (int j = 0; j < 4; j++) {
        float4 lo = make_float4(acc[0][j], acc[1][j], acc[2][j], acc[3][j]);
        float4 hi = make_float4(acc[4][j], acc[5][j], acc[6][j], acc[7][j]);
        *(float4*)(g_BxT + base + (size_t)j * SEQ)     = lo;
        *(float4*)(g_BxT + base + (size_t)j * SEQ + 4) = hi;
    }
}

// ---------------------------------------------------------------------------
// Stage 2: out[b,n,o] = SCALING * sum_r Bx[b,r,n] * At[b,r,o]
// Block: 64 n x 64 o tile, full r=64 reduction.
// Both smem tiles loaded in natural [r][*] layout (no transposed stores,
// no bank conflicts), float4 everywhere.
// grid: (DOUT/64, SEQ/64, BATCH)
// ---------------------------------------------------------------------------
__global__ __launch_bounds__(256) void stage2_kernel(float* __restrict__ out) {
    __shared__ float ps[64][68];  // Bx tile [r][n]
    __shared__ float as[64][68];  // A  tile [r][o]
    int b  = blockIdx.z;
    int nt = blockIdx.y;
    int ot = blockIdx.x;
    const float* Bxp = g_BxT + (size_t)b * RANK * SEQ  + (size_t)nt * 64;
    const float* Ap  = g_At  + (size_t)b * RANK * DOUT + (size_t)ot * 64;
    int tid = threadIdx.x;
    int tx = tid & 15;
    int ty = tid >> 4;

    // 64 rows x 64 floats each = 1024 float4 per tile, 4 per thread
    #pragma unroll
    for (int t = 0; t < 4; t++) {
        int idx = tid + t * 256;
        int row = idx >> 4;       // r
        int cv  = idx & 15;       // float4 within row
        float4 v = *(const float4*)(Bxp + (size_t)row * SEQ + cv * 4);
        *(float4*)&ps[row][cv * 4] = v;
        float4 w = *(const float4*)(Ap + (size_t)row * DOUT + cv * 4);
        *(float4*)&as[row][cv * 4] = w;
    }
    __syncthreads();

    float acc[4][4];
    #pragma unroll
    for (int i = 0; i < 4; i++)
        #pragma unroll
        for (int j = 0; j < 4; j++) acc[i][j] = 0.f;

    #pragma unroll 16
    for (int r = 0; r < 64; r++) {
        float4 av = *(const float4*)&ps[r][ty * 4];
        float4 bv = *(const float4*)&as[r][tx * 4];
        float a[4]  = {av.x, av.y, av.z, av.w};
        float bb[4] = {bv.x, bv.y, bv.z, bv.w};
        #pragma unroll
        for (int i = 0; i < 4; i++)
            #pragma unroll
            for (int j = 0; j < 4; j++)
                acc[i][j] = fmaf(a[i], bb[j], acc[i][j]);
    }

    size_t obase = ((size_t)b * SEQ + (size_t)nt * 64 + (size_t)ty * 4) * DOUT
                 + (size_t)ot * 64 + (size_t)tx * 4;
    #pragma unroll
    for (int i = 0; i < 4; i++) {
        float4 v = make_float4(acc[i][0] * SCALING, acc[i][1] * SCALING,
                               acc[i][2] * SCALING, acc[i][3] * SCALING);
        *(float4*)(out + obase + (size_t)i * DOUT) = v;
    }
}

// ---------------------------------------------------------------------------
extern "C" void kernel_launch(void* const* d_in, const int* in_sizes, int n_in,
                              void* d_out, int out_size) {
    const float* x   = (const float*)d_in[0];
    const int*   ids = (const int*)  d_in[1];
    const float* A   = (const float*)d_in[2];
    const float* B   = (const float*)d_in[3];
    float* out = (float*)d_out;

    norm_ids_kernel<<<1, 32>>>(ids);

    dim3 gT(DOUT / 32, RANK / 32, BATCH);
    transposeA_kernel<<<gT, dim3(32, 8)>>>(A);

    dim3 g1(SEQ / 128, BATCH);
    stage1_kernel<<<g1, 256>>>(x, B);

    dim3 g2(DOUT / 64, SEQ / 64, BATCH);
    stage2_kernel<<<g2, 256>>>(out);

    (void)in_sizes; (void)n_in; (void)out_size;
}

// round 2
// speedup vs baseline: 1.0557x; 1.0557x over previous
#include <cuda_runtime.h>
#include <cstdint>

#define BATCH 16
#define SEQ   2048
#define DIN   4096
#define DOUT  4096
#define RANK  64
#define KSPLIT 4
#define KRANGE (DIN / KSPLIT)      // 1024
#define SCALING (1.0f/64.0f)

// Scratch (device globals: allocation-free per harness rules)
// Bx partial sums: [ks][b][r][n]  (4 * 16 * 64 * 2048 floats = 32 MB)
__device__ float g_Bx[(size_t)KSPLIT * BATCH * RANK * SEQ];
__device__ int   g_ids[BATCH];

// packed fp32x2 helpers (ptxas never emits FFMA2 from C++; must be inline PTX)
#define FMA2(d, a, b) asm("fma.rn.f32x2 %0, %1, %2, %0;" : "+l"(d) : "l"(a), "l"(b))
#define MUL2(d, a, b) asm("mul.rn.f32x2 %0, %1, %2;" : "=l"(d) : "l"(a), "l"(b))
#define PACK2(d, s)   asm("mov.b64 %0, {%1, %1};" : "=l"(d) : "f"(s))

// ---------------------------------------------------------------------------
// adapter_ids may arrive as int32 or int64 (jax x64 off canonicalizes to i32).
// int64-LE data viewed as int32 has all odd positions == 0 (ids < 64).
// Only the first 64 bytes are read before deciding (safe for either dtype).
// ---------------------------------------------------------------------------
__global__ void norm_ids_kernel(const int* __restrict__ raw) {
    if (threadIdx.x == 0) {
        bool odd_zero = true;
        #pragma unroll
        for (int i = 1; i < 16; i += 2) odd_zero &= (raw[i] == 0);
        if (odd_zero) {
            const long long* r64 = (const long long*)raw;
            for (int i = 0; i < BATCH; i++) g_ids[i] = (int)r64[i];
        } else {
            for (int i = 0; i < BATCH; i++) g_ids[i] = raw[i];
        }
    }
}

// ---------------------------------------------------------------------------
// Stage 1: Bx_partial[ks][b][r][n] = sum_{k in ks range} x[b,n,k] * B[aid_b,r,k]
// Tile: 128 n x 64 r, K-tile 32, 128 threads, 8x8 outputs/thread.
// Accumulators are f32x2 pairs along n (contiguous in the [r][n] output).
// grid: (SEQ/128, BATCH, KSPLIT)
// ---------------------------------------------------------------------------
__global__ __launch_bounds__(128, 4) void stage1_kernel(const float* __restrict__ x,
                                                        const float* __restrict__ Bm) {
    __shared__ float xs[32][132];  // [k][n]
    __shared__ float bs[32][68];   // [k][r]
    const int nt = blockIdx.x;
    const int b  = blockIdx.y;
    const int ks = blockIdx.z;
    const int aid = g_ids[b];
    const float* xp = x  + ((size_t)b * SEQ + (size_t)nt * 128) * DIN + (size_t)ks * KRANGE;
    const float* Bp = Bm + (size_t)aid * RANK * DIN + (size_t)ks * KRANGE;
    const int tid = threadIdx.x;
    const int tx = tid & 7;    // r group: r = tx*8 + j
    const int ty = tid >> 3;   // n group: n = ty*8 + 2i+{0,1}

    unsigned long long acc[4][8];
    #pragma unroll
    for (int i = 0; i < 4; i++)
        #pragma unroll
        for (int j = 0; j < 8; j++) acc[i][j] = 0ULL;

    for (int k0 = 0; k0 < KRANGE; k0 += 32) {
        // x tile: 128 rows x 32 k = 1024 float4, 8 per thread, transposed store
        #pragma unroll
        for (int t = 0; t < 8; t++) {
            int idx = tid + t * 128;
            int row = idx >> 3;
            int cv  = idx & 7;
            float4 v = *(const float4*)(xp + (size_t)row * DIN + k0 + cv * 4);
            xs[cv*4+0][row] = v.x; xs[cv*4+1][row] = v.y;
            xs[cv*4+2][row] = v.z; xs[cv*4+3][row] = v.w;
        }
        // B tile: 64 rows x 32 k = 512 float4, 4 per thread
        #pragma unroll
        for (int t = 0; t < 4; t++) {
            int idx = tid + t * 128;
            int row = idx >> 3;
            int cv  = idx & 7;
            float4 v = *(const float4*)(Bp + (size_t)row * DIN + k0 + cv * 4);
            bs[cv*4+0][row] = v.x; bs[cv*4+1][row] = v.y;
            bs[cv*4+2][row] = v.z; bs[cv*4+3][row] = v.w;
        }
        __syncthreads();
        #pragma unroll
        for (int kk = 0; kk < 32; kk++) {
            // a: 8 consecutive n as 4 f32x2 pairs (natural layout)
            ulonglong2 a01 = *(const ulonglong2*)&xs[kk][ty * 8];
            ulonglong2 a23 = *(const ulonglong2*)&xs[kk][ty * 8 + 4];
            unsigned long long a2[4] = {a01.x, a01.y, a23.x, a23.y};
            // b: 8 r scalars, broadcast-packed into dup pairs (ALU pipe)
            float4 b0 = *(const float4*)&bs[kk][tx * 8];
            float4 b1 = *(const float4*)&bs[kk][tx * 8 + 4];
            float bf[8] = {b0.x, b0.y, b0.z, b0.w, b1.x, b1.y, b1.z, b1.w};
            unsigned long long bd[8];
            #pragma unroll
            for (int j = 0; j < 8; j++) PACK2(bd[j], bf[j]);
            #pragma unroll
            for (int i = 0; i < 4; i++)
                #pragma unroll
                for (int j = 0; j < 8; j++)
                    FMA2(acc[i][j], a2[i], bd[j]);
        }
        __syncthreads();
    }

    // Store partial: g_Bx[ks][b][r = tx*8+j][n = nt*128 + ty*8 ..]
    float* outp = g_Bx + (((size_t)ks * BATCH + b) * RANK + (size_t)tx * 8) * SEQ
                + (size_t)nt * 128 + (size_t)ty * 8;
    #pragma unroll
    for (int j = 0; j < 8; j++) {
        ulonglong2 lo = make_ulonglong2(acc[0][j], acc[1][j]);
        ulonglong2 hi = make_ulonglong2(acc[2][j], acc[3][j]);
        *(ulonglong2*)(outp + (size_t)j * SEQ)     = lo;
        *(ulonglong2*)(outp + (size_t)j * SEQ + 4) = hi;
    }
}

// ---------------------------------------------------------------------------
// Stage 2: out[b,n,o] = SCALING * sum_r (sum_ks Bx[ks,b,r,n]) * A[aid_b,o,r]
// Tile: 128 n x 128 o, r-chunks of 32, 256 threads, 8x8 outputs/thread.
// A transposed into smem during tile fill (no separate transpose pass).
// ps tile fill sums the 4 K-split partials.
// Accumulators are f32x2 pairs along o (contiguous output).
// grid: (DOUT/128, SEQ/128, BATCH)
// ---------------------------------------------------------------------------
__global__ __launch_bounds__(256, 2) void stage2_kernel(const float* __restrict__ Am,
                                                        float* __restrict__ out) {
    __shared__ float ps[32][132];  // Bx tile [r][n], K-split partials summed
    __shared__ float as[32][132];  // A  tile [r][o]
    const int ot = blockIdx.x;
    const int nt = blockIdx.y;
    const int b  = blockIdx.z;
    const int aid = g_ids[b];
    const int tid = threadIdx.x;
    const int tx = tid & 15;   // o group: o = tx*8 + 2j+{0,1}
    const int ty = tid >> 4;   // n group: n = ty*8 + i

    const float* Ap = Am + (size_t)aid * DOUT * RANK + (size_t)ot * 128 * RANK;
    const float* Bxp = g_Bx + ((size_t)b * RANK) * SEQ + (size_t)nt * 128;
    const size_t PSTRIDE = (size_t)BATCH * RANK * SEQ;  // between K-split partials

    unsigned long long acc[8][4];
    #pragma unroll
    for (int i = 0; i < 8; i++)
        #pragma unroll
        for (int j = 0; j < 4; j++) acc[i][j] = 0ULL;

    #pragma unroll
    for (int c = 0; c < 2; c++) {           // r chunks of 32
        const int r0 = c * 32;
        // ps fill: 32 r x 128 n = 1024 float4, 4/thread, sum 4 partials
        #pragma unroll
        for (int t = 0; t < 4; t++) {
            int idx = tid + t * 256;
            int rr  = idx >> 5;        // 32 float4 per row
            int cv  = idx & 31;
            const float* p = Bxp + (size_t)(r0 + rr) * SEQ + cv * 4;
            float4 v0 = *(const float4*)(p);
            float4 v1 = *(const float4*)(p + PSTRIDE);
            float4 v2 = *(const float4*)(p + 2 * PSTRIDE);
            float4 v3 = *(const float4*)(p + 3 * PSTRIDE);
            float4 s;
            s.x = (v0.x + v1.x) + (v2.x + v3.x);
            s.y = (v0.y + v1.y) + (v2.y + v3.y);
            s.z = (v0.z + v1.z) + (v2.z + v3.z);
            s.w = (v0.w + v1.w) + (v2.w + v3.w);
            *(float4*)&ps[rr][cv * 4] = s;
        }
        // as fill: transpose A[o][r] -> as[r][o]. 128 o x 32 r = 1024 f4, 4/thread
        #pragma unroll
        for (int t = 0; t < 4; t++) {
            int idx = tid + t * 256;
            int ol  = idx >> 3;        // 8 float4 per o-row (32 r)
            int q   = idx & 7;
            float4 v = *(const float4*)(Ap + (size_t)ol * RANK + r0 + q * 4);
            as[q*4+0][ol] = v.x; as[q*4+1][ol] = v.y;
            as[q*4+2][ol] = v.z; as[q*4+3][ol] = v.w;
        }
        __syncthreads();
        #pragma unroll
        for (int r = 0; r < 32; r++) {
            // a: ps scalar per n, broadcast-packed
            float4 a0 = *(const float4*)&ps[r][ty * 8];
            float4 a1 = *(const float4*)&ps[r][ty * 8 + 4];
            float af[8] = {a0.x, a0.y, a0.z, a0.w, a1.x, a1.y, a1.z, a1.w};
            unsigned long long ad[8];
            #pragma unroll
            for (int i = 0; i < 8; i++) PACK2(ad[i], af[i]);
            // b: 8 consecutive o as 4 natural f32x2 pairs
            ulonglong2 b01 = *(const ulonglong2*)&as[r][tx * 8];
            ulonglong2 b23 = *(const ulonglong2*)&as[r][tx * 8 + 4];
            unsigned long long b2[4] = {b01.x, b01.y, b23.x, b23.y};
            #pragma unroll
            for (int i = 0; i < 8; i++)
                #pragma unroll
                for (int j = 0; j < 4; j++)
                    FMA2(acc[i][j], ad[i], b2[j]);
        }
        __syncthreads();
    }

    // scale + store: per n row i, 8 consecutive o = 2 float4
    unsigned long long sc2;
    PACK2(sc2, SCALING);
    size_t obase = ((size_t)b * SEQ + (size_t)nt * 128 + (size_t)ty * 8) * DOUT
                 + (size_t)ot * 128 + (size_t)tx * 8;
    #pragma unroll
    for (int i = 0; i < 8; i++) {
        unsigned long long s0, s1, s2, s3;
        MUL2(s0, acc[i][0], sc2);
        MUL2(s1, acc[i][1], sc2);
        MUL2(s2, acc[i][2], sc2);
        MUL2(s3, acc[i][3], sc2);
        *(ulonglong2*)(out + obase + (size_t)i * DOUT)     = make_ulonglong2(s0, s1);
        *(ulonglong2*)(out + obase + (size_t)i * DOUT + 4) = make_ulonglong2(s2, s3);
    }
}

// ---------------------------------------------------------------------------
extern "C" void kernel_launch(void* const* d_in, const int* in_sizes, int n_in,
                              void* d_out, int out_size) {
    const float* x   = (const float*)d_in[0];
    const int*   ids = (const int*)  d_in[1];
    const float* A   = (const float*)d_in[2];
    const float* B   = (const float*)d_in[3];
    float* out = (float*)d_out;

    norm_ids_kernel<<<1, 32>>>(ids);

    dim3 g1(SEQ / 128, BATCH, KSPLIT);
    stage1_kernel<<<g1, 128>>>(x, B);

    dim3 g2(DOUT / 128, SEQ / 128, BATCH);
    stage2_kernel<<<g2, 256>>>(A, out);

    (void)in_sizes; (void)n_in; (void)out_size;
}

// round 4
// speedup vs baseline: 2.0214x; 1.9148x over previous
#include <cuda_runtime.h>
#include <cuda_bf16.h>
#include <cstdint>

#define BATCH 16
#define SEQ   2048
#define DIN   4096
#define DOUT  4096
#define RANK  64
#define SCALING (1.0f/64.0f)

// ---------------- device scratch (no allocations allowed) -------------------
__device__ unsigned short g_Bh[(size_t)BATCH * RANK * DIN];   // B hi [b][r][k]
__device__ unsigned short g_Bl[(size_t)BATCH * RANK * DIN];   // B lo
__device__ unsigned short g_Ah[(size_t)BATCH * DOUT * RANK];  // A hi [b][o][r]
__device__ unsigned short g_Al[(size_t)BATCH * DOUT * RANK];  // A lo
__device__ int g_ids[BATCH];

// ---------------- helpers ----------------------------------------------------
__device__ __forceinline__ uint32_t smem_u32(const void* p) {
    uint32_t a;
    asm("{ .reg .u64 t; cvta.to.shared.u64 t, %1; cvt.u32.u64 %0, t; }"
        : "=r"(a) : "l"(p));
    return a;
}
#define SW128(o) ((uint32_t)(o) ^ ((((uint32_t)(o)) >> 3) & 0x70))

__device__ __forceinline__ uint32_t packbf(float a, float b) {
    unsigned short ua = __bfloat16_as_ushort(__float2bfloat16(a));
    unsigned short ub = __bfloat16_as_ushort(__float2bfloat16(b));
    return (uint32_t)ua | ((uint32_t)ub << 16);
}
__device__ __forceinline__ float hi_of(float v) {
    return __bfloat162float(__float2bfloat16(v));
}

// ldmatrix x4 (portable PTX, sm_75+): 4 8x8 b16 matrices
#define LDSM4(r0, r1, r2, r3, addr) \
    asm volatile("ldmatrix.sync.aligned.m8n8.x4.shared.b16 {%0,%1,%2,%3}, [%4];" \
        : "=r"(r0), "=r"(r1), "=r"(r2), "=r"(r3) : "r"(addr))

// mma.sync bf16 (portable PTX, sm_80+): executes as HMMA on sm_103
#define MMA(d, a, b0v, b1v) \
    asm volatile("mma.sync.aligned.m16n8k16.row.col.f32.bf16.bf16.f32 " \
        "{%0,%1,%2,%3}, {%4,%5,%6,%7}, {%8,%9}, {%0,%1,%2,%3};" \
        : "+f"((d)[0]), "+f"((d)[1]), "+f"((d)[2]), "+f"((d)[3]) \
        : "r"((a)[0]), "r"((a)[1]), "r"((a)[2]), "r"((a)[3]), "r"(b0v), "r"(b1v))

// ---------------------------------------------------------------------------
// adapter_ids dtype detection (int64 vs int32)
// ---------------------------------------------------------------------------
__global__ void norm_ids_kernel(const int* __restrict__ raw) {
    if (threadIdx.x == 0) {
        bool odd_zero = true;
        #pragma unroll
        for (int i = 1; i < 16; i += 2) odd_zero &= (raw[i] == 0);
        if (odd_zero) {
            const long long* r64 = (const long long*)raw;
            for (int i = 0; i < BATCH; i++) g_ids[i] = (int)r64[i];
        } else {
            for (int i = 0; i < BATCH; i++) g_ids[i] = raw[i];
        }
    }
}

// ---------------------------------------------------------------------------
// Split requested A/B adapter slices into bf16 hi/lo (contiguous 1MB blocks).
// grid (256, BATCH, 2), block 256. z=0: B, z=1: A.
// ---------------------------------------------------------------------------
__global__ __launch_bounds__(256) void split_kernel(const float* __restrict__ Am,
                                                    const float* __restrict__ Bm) {
    const int b = blockIdx.y;
    const int aid = g_ids[b];
    const int which = blockIdx.z;
    const size_t i4 = (size_t)blockIdx.x * 256 + threadIdx.x;
    const size_t PER = (size_t)RANK * DIN;   // 262144 for both A and B slices
    const float* src = (which ? Am : Bm) + (size_t)aid * PER + i4 * 4;
    unsigned short* dh = (which ? g_Ah : g_Bh) + (size_t)b * PER + i4 * 4;
    unsigned short* dl = (which ? g_Al : g_Bl) + (size_t)b * PER + i4 * 4;
    float4 v = *(const float4*)src;
    float hx = hi_of(v.x), hy = hi_of(v.y), hz = hi_of(v.z), hw = hi_of(v.w);
    *(uint2*)dh = make_uint2(packbf(v.x, v.y), packbf(v.z, v.w));
    *(uint2*)dl = make_uint2(packbf(v.x - hx, v.y - hy), packbf(v.z - hz, v.w - hw));
}

// ---------------------------------------------------------------------------
// Fused LoRA kernel. CTA = (128-n tile, batch). 8 warps, warp owns 16 n-rows.
// Stage 1: Bx[16x64] per warp via mma.sync over K=4096 (3-term bf16 split).
// In-register D-frag -> A-frag conversion (no smem, no global round-trip).
// Stage 2: out[16n x 4096o] per warp, o-tiles of 64, smem-bounced stores.
// smem (51200 B):
//   stage1: XH @0 (16K), XL @16K (16K), BH @32K (8K), BL @40K (8K)
//   stage2: AH @0 (8K),  AL @8K (8K),   bounce @16K (8*16*68*4 = 34816)
// ---------------------------------------------------------------------------
#define S_XH 0
#define S_XL 16384
#define S_BH 32768
#define S_BL 40960
#define S_AH 0
#define S_AL 8192
#define S_BOUNCE 16384
#define SMEM_TOTAL 51200

__global__ __launch_bounds__(256, 2) void fused_kernel(const float* __restrict__ x,
                                                       float* __restrict__ out) {
    extern __shared__ char smem[];
    const uint32_t sb = smem_u32(smem);
    const int tid = threadIdx.x;
    const int w = tid >> 5;
    const int lane = tid & 31;
    const int nt = blockIdx.x;
    const int b = blockIdx.y;

    const float* xp = x + ((size_t)b * SEQ + (size_t)nt * 128) * DIN;
    const unsigned short* bhp = g_Bh + (size_t)b * RANK * DIN;
    const unsigned short* blp = g_Bl + (size_t)b * RANK * DIN;

    // ldmatrix per-thread address components (same formula for A and B frags)
    const int lrow = lane & 15;
    const int lkb = (lane >> 4) * 16;

    // ======================= STAGE 1 ========================================
    float acc[8][4];
    #pragma unroll
    for (int i = 0; i < 8; i++)
        #pragma unroll
        for (int j = 0; j < 4; j++) acc[i][j] = 0.f;

    float4 px[8];
    uint4 pbh[2], pbl[2];
    // prefetch chunk 0
    #pragma unroll
    for (int t = 0; t < 8; t++) {
        int idx = tid + t * 256;
        px[t] = *(const float4*)(xp + (size_t)(idx >> 4) * DIN + (idx & 15) * 4);
    }
    #pragma unroll
    for (int t = 0; t < 2; t++) {
        int idx = tid + t * 256;
        size_t e = (size_t)(idx >> 3) * DIN + (idx & 7) * 8;
        pbh[t] = *(const uint4*)(bhp + e);
        pbl[t] = *(const uint4*)(blp + e);
    }

    for (int c = 0; c < 64; c++) {
        __syncthreads();
        // store prefetched tiles (split x fp32 -> bf16 hi/lo)
        #pragma unroll
        for (int t = 0; t < 8; t++) {
            int idx = tid + t * 256;
            int row = idx >> 4, cv = idx & 15;
            float4 v = px[t];
            float hx = hi_of(v.x), hy = hi_of(v.y), hz = hi_of(v.z), hw = hi_of(v.w);
            uint32_t off = SW128(row * 128 + cv * 8);
            *(uint2*)(smem + S_XH + off) = make_uint2(packbf(v.x, v.y), packbf(v.z, v.w));
            *(uint2*)(smem + S_XL + off) =
                make_uint2(packbf(v.x - hx, v.y - hy), packbf(v.z - hz, v.w - hw));
        }
        #pragma unroll
        for (int t = 0; t < 2; t++) {
            int idx = tid + t * 256;
            int row = idx >> 3, cv = idx & 7;
            uint32_t off = SW128(row * 128 + cv * 16);
            *(uint4*)(smem + S_BH + off) = pbh[t];
            *(uint4*)(smem + S_BL + off) = pbl[t];
        }
        __syncthreads();
        // prefetch next chunk (overlaps the mma work below)
        if (c < 63) {
            int k0 = (c + 1) * 64;
            #pragma unroll
            for (int t = 0; t < 8; t++) {
                int idx = tid + t * 256;
                px[t] = *(const float4*)(xp + (size_t)(idx >> 4) * DIN + k0 + (idx & 15) * 4);
            }
            #pragma unroll
            for (int t = 0; t < 2; t++) {
                int idx = tid + t * 256;
                size_t e = (size_t)(idx >> 3) * DIN + k0 + (idx & 7) * 8;
                pbh[t] = *(const uint4*)(bhp + e);
                pbl[t] = *(const uint4*)(blp + e);
            }
        }
        // mma over 4 k16 sub-chunks
        #pragma unroll
        for (int kc = 0; kc < 4; kc++) {
            uint32_t ah[4], al[4];
            uint32_t aoff = SW128((w * 16 + lrow) * 128 + kc * 32 + lkb);
            LDSM4(ah[0], ah[1], ah[2], ah[3], sb + S_XH + aoff);
            LDSM4(al[0], al[1], al[2], al[3], sb + S_XL + aoff);
            #pragma unroll
            for (int nb = 0; nb < 4; nb++) {
                uint32_t bh[4], bl[4];
                uint32_t boff = SW128((nb * 16 + lrow) * 128 + kc * 32 + lkb);
                LDSM4(bh[0], bh[1], bh[2], bh[3], sb + S_BH + boff);
                LDSM4(bl[0], bl[1], bl[2], bl[3], sb + S_BL + boff);
                MMA(acc[2 * nb],     ah, bh[0], bh[2]);
                MMA(acc[2 * nb],     ah, bl[0], bl[2]);
                MMA(acc[2 * nb],     al, bh[0], bh[2]);
                MMA(acc[2 * nb + 1], ah, bh[1], bh[3]);
                MMA(acc[2 * nb + 1], ah, bl[1], bl[3]);
                MMA(acc[2 * nb + 1], al, bh[1], bh[3]);
            }
        }
    }

    // In-register conversion: stage1 D-frags -> stage2 A-frags (bf16 hi/lo).
    // a-frag[kc] = { (r,2c), (r+8,2c), (r,2c+8), (r+8,2c+8) } over k=r-dim:
    //   [kc][0] = pack(acc[2kc][0],acc[2kc][1])      [kc][1] = pack(acc[2kc][2],[3])
    //   [kc][2] = pack(acc[2kc+1][0],[1])            [kc][3] = pack(acc[2kc+1][2],[3])
    uint32_t bxh[4][4], bxl[4][4];
    #pragma unroll
    for (int kc = 0; kc < 4; kc++) {
        #pragma unroll
        for (int h = 0; h < 2; h++) {
            float* d = acc[2 * kc + h];
            float h0 = hi_of(d[0]), h1 = hi_of(d[1]), h2 = hi_of(d[2]), h3 = hi_of(d[3]);
            bxh[kc][2 * h]     = packbf(d[0], d[1]);
            bxh[kc][2 * h + 1] = packbf(d[2], d[3]);
            bxl[kc][2 * h]     = packbf(d[0] - h0, d[1] - h1);
            bxl[kc][2 * h + 1] = packbf(d[2] - h2, d[3] - h3);
        }
    }

    // ======================= STAGE 2 ========================================
    const unsigned short* ahp = g_Ah + (size_t)b * DOUT * RANK;
    const unsigned short* alp = g_Al + (size_t)b * DOUT * RANK;
    float* bp = (float*)(smem + S_BOUNCE) + w * 16 * 68;
    const int r0 = lane >> 2;
    const int c0 = 2 * (lane & 3);

    uint4 pah[2], pal[2];
    #pragma unroll
    for (int t = 0; t < 2; t++) {
        int idx = tid + t * 256;
        size_t e = (size_t)(idx >> 3) * RANK + (idx & 7) * 8;
        pah[t] = *(const uint4*)(ahp + e);
        pal[t] = *(const uint4*)(alp + e);
    }

    for (int ot = 0; ot < 64; ot++) {
        __syncthreads();
        #pragma unroll
        for (int t = 0; t < 2; t++) {
            int idx = tid + t * 256;
            int row = idx >> 3, cv = idx & 7;
            uint32_t off = SW128(row * 128 + cv * 16);
            *(uint4*)(smem + S_AH + off) = pah[t];
            *(uint4*)(smem + S_AL + off) = pal[t];
        }
        __syncthreads();
        if (ot < 63) {
            size_t obase = (size_t)(ot + 1) * 64 * RANK;
            #pragma unroll
            for (int t = 0; t < 2; t++) {
                int idx = tid + t * 256;
                size_t e = obase + (size_t)(idx >> 3) * RANK + (idx & 7) * 8;
                pah[t] = *(const uint4*)(ahp + e);
                pal[t] = *(const uint4*)(alp + e);
            }
        }
        #pragma unroll
        for (int nb = 0; nb < 4; nb++) {        // o-blocks of 16
            float d2[2][4];
            #pragma unroll
            for (int h = 0; h < 2; h++)
                #pragma unroll
                for (int j = 0; j < 4; j++) d2[h][j] = 0.f;
            #pragma unroll
            for (int kc = 0; kc < 4; kc++) {
                uint32_t Ah[4], Al[4];
                uint32_t off = SW128((nb * 16 + lrow) * 128 + kc * 32 + lkb);
                LDSM4(Ah[0], Ah[1], Ah[2], Ah[3], sb + S_AH + off);
                LDSM4(Al[0], Al[1], Al[2], Al[3], sb + S_AL + off);
                MMA(d2[0], bxh[kc], Ah[0], Ah[2]);
                MMA(d2[0], bxh[kc], Al[0], Al[2]);
                MMA(d2[0], bxl[kc], Ah[0], Ah[2]);
                MMA(d2[1], bxh[kc], Ah[1], Ah[3]);
                MMA(d2[1], bxh[kc], Al[1], Al[3]);
                MMA(d2[1], bxl[kc], Ah[1], Ah[3]);
            }
            // scale + bounce (per-warp region)
            *(float2*)(bp + r0 * 68 + nb * 16 + c0) =
                make_float2(d2[0][0] * SCALING, d2[0][1] * SCALING);
            *(float2*)(bp + (r0 + 8) * 68 + nb * 16 + c0) =
                make_float2(d2[0][2] * SCALING, d2[0][3] * SCALING);
            *(float2*)(bp + r0 * 68 + nb * 16 + 8 + c0) =
                make_float2(d2[1][0] * SCALING, d2[1][1] * SCALING);
            *(float2*)(bp + (r0 + 8) * 68 + nb * 16 + 8 + c0) =
                make_float2(d2[1][2] * SCALING, d2[1][3] * SCALING);
        }
        __syncwarp();
        // coalesced stores: 16 rows x 64 floats, 256B segments
        #pragma unroll
        for (int j = 0; j < 8; j++) {
            int row = j * 2 + (lane >> 4);
            int c4 = lane & 15;
            float4 v = *(const float4*)(bp + row * 68 + c4 * 4);
            *(float4*)(out + ((size_t)b * SEQ + (size_t)nt * 128 + w * 16 + row) * DOUT
                           + ot * 64 + c4 * 4) = v;
        }
        __syncwarp();
    }
}

// ---------------------------------------------------------------------------
extern "C" void kernel_launch(void* const* d_in, const int* in_sizes, int n_in,
                              void* d_out, int out_size) {
    const float* x   = (const float*)d_in[0];
    const int*   ids = (const int*)  d_in[1];
    const float* A   = (const float*)d_in[2];
    const float* B   = (const float*)d_in[3];
    float* out = (float*)d_out;

    cudaFuncSetAttribute(fused_kernel, cudaFuncAttributeMaxDynamicSharedMemorySize,
                         SMEM_TOTAL);

    norm_ids_kernel<<<1, 32>>>(ids);

    dim3 gS(256, BATCH, 2);
    split_kernel<<<gS, 256>>>(A, B);

    dim3 gF(SEQ / 128, BATCH);
    fused_kernel<<<gF, 256, SMEM_TOTAL>>>(x, out);

    (void)in_sizes; (void)n_in; (void)out_size;
}

// round 5
// speedup vs baseline: 2.4973x; 1.2354x over previous
#include <cuda_runtime.h>
#include <cuda_fp16.h>
#include <cstdint>

#define BATCH 16
#define SEQ   2048
#define DIN   4096
#define DOUT  4096
#define RANK  64
#define SCALING (1.0f/64.0f)

// ---------------- device scratch (no allocations allowed) -------------------
// B and A pre-scaled by 64 and split into fp16 hi/lo (keeps lo parts normal).
__device__ unsigned short g_Bh[(size_t)BATCH * RANK * DIN];   // 64*B hi [b][r][k]
__device__ unsigned short g_Bl[(size_t)BATCH * RANK * DIN];   // 64*B lo
__device__ unsigned short g_Ah[(size_t)BATCH * DOUT * RANK];  // 64*A hi [b][o][r]
__device__ unsigned short g_Al[(size_t)BATCH * DOUT * RANK];  // 64*A lo
__device__ int g_ids[BATCH];

// ---------------- helpers ----------------------------------------------------
__device__ __forceinline__ uint32_t smem_u32(const void* p) {
    uint32_t a;
    asm("{ .reg .u64 t; cvta.to.shared.u64 t, %1; cvt.u32.u64 %0, t; }"
        : "=r"(a) : "l"(p));
    return a;
}
#define SW128(o) ((uint32_t)(o) ^ ((((uint32_t)(o)) >> 3) & 0x70))

__device__ __forceinline__ uint32_t h2u(__half2 h) {
    return *reinterpret_cast<uint32_t*>(&h);
}

// ldmatrix x4 (portable PTX, sm_75+)
#define LDSM4(r0, r1, r2, r3, addr) \
    asm volatile("ldmatrix.sync.aligned.m8n8.x4.shared.b16 {%0,%1,%2,%3}, [%4];" \
        : "=r"(r0), "=r"(r1), "=r"(r2), "=r"(r3) : "r"(addr))

// mma.sync fp16 (portable PTX, sm_80+)
#define MMA(d, a, b0v, b1v) \
    asm volatile("mma.sync.aligned.m16n8k16.row.col.f32.f16.f16.f32 " \
        "{%0,%1,%2,%3}, {%4,%5,%6,%7}, {%8,%9}, {%0,%1,%2,%3};" \
        : "+f"((d)[0]), "+f"((d)[1]), "+f"((d)[2]), "+f"((d)[3]) \
        : "r"((a)[0]), "r"((a)[1]), "r"((a)[2]), "r"((a)[3]), "r"(b0v), "r"(b1v))

// ---------------------------------------------------------------------------
// adapter_ids dtype detection (int64 vs int32)
// ---------------------------------------------------------------------------
__global__ void norm_ids_kernel(const int* __restrict__ raw) {
    if (threadIdx.x == 0) {
        bool odd_zero = true;
        #pragma unroll
        for (int i = 1; i < 16; i += 2) odd_zero &= (raw[i] == 0);
        if (odd_zero) {
            const long long* r64 = (const long long*)raw;
            for (int i = 0; i < BATCH; i++) g_ids[i] = (int)r64[i];
        } else {
            for (int i = 0; i < BATCH; i++) g_ids[i] = raw[i];
        }
    }
}

// ---------------------------------------------------------------------------
// Split requested A/B adapter slices into fp16 hi/lo, pre-scaled by 64.
// grid (256, BATCH, 2), block 256. z=0: B, z=1: A.
// ---------------------------------------------------------------------------
__global__ __launch_bounds__(256) void split_kernel(const float* __restrict__ Am,
                                                    const float* __restrict__ Bm) {
    const int b = blockIdx.y;
    const int aid = g_ids[b];
    const int which = blockIdx.z;
    const size_t i4 = (size_t)blockIdx.x * 256 + threadIdx.x;
    const size_t PER = (size_t)RANK * DIN;
    const float* src = (which ? Am : Bm) + (size_t)aid * PER + i4 * 4;
    unsigned short* dh = (which ? g_Ah : g_Bh) + (size_t)b * PER + i4 * 4;
    unsigned short* dl = (which ? g_Al : g_Bl) + (size_t)b * PER + i4 * 4;
    float4 v = *(const float4*)src;
    v.x *= 64.f; v.y *= 64.f; v.z *= 64.f; v.w *= 64.f;
    __half2 h01 = __floats2half2_rn(v.x, v.y);
    __half2 h23 = __floats2half2_rn(v.z, v.w);
    float2 f01 = __half22float2(h01);
    float2 f23 = __half22float2(h23);
    __half2 l01 = __floats2half2_rn(v.x - f01.x, v.y - f01.y);
    __half2 l23 = __floats2half2_rn(v.z - f23.x, v.w - f23.y);
    *(uint2*)dh = make_uint2(h2u(h01), h2u(h23));
    *(uint2*)dl = make_uint2(h2u(l01), h2u(l23));
}

// ---------------------------------------------------------------------------
// Fused LoRA kernel (2-term fp16 split).
// CTA = (128-n tile, batch). 8 warps, warp owns 16 n-rows.
// Stage 1: Y[16x64] = x_hi @ (64B)        (per warp, K=4096, 2 MMAs/k16)
// Stage 2: out = fp16(Y*2^-12) @ (64A) * (1/64)
// smem, double-buffered:
//   stage1 buffer stride 32768: XH @+0 (16K), BH @+16384 (8K), BL @+24576 (8K)
//   stage2 buffer stride 16384: AH @+0 (8K),  AL @+8192 (8K)
//   bounce @32768 (34816)
// ---------------------------------------------------------------------------
#define S1_STRIDE 32768
#define S1_BH 16384
#define S1_BL 24576
#define S2_STRIDE 16384
#define S2_AL 8192
#define S_BOUNCE 32768
#define SMEM_TOTAL 67584

__global__ __launch_bounds__(256, 2) void fused_kernel(const float* __restrict__ x,
                                                       float* __restrict__ out) {
    extern __shared__ char smem[];
    const uint32_t sb = smem_u32(smem);
    const int tid = threadIdx.x;
    const int w = tid >> 5;
    const int lane = tid & 31;
    const int nt = blockIdx.x;
    const int b = blockIdx.y;

    const float* xp = x + ((size_t)b * SEQ + (size_t)nt * 128) * DIN;
    const unsigned short* bhp = g_Bh + (size_t)b * RANK * DIN;
    const unsigned short* blp = g_Bl + (size_t)b * RANK * DIN;

    const int lrow = lane & 15;
    const int lkb = (lane >> 4) * 16;

    // ======================= STAGE 1 ========================================
    float acc[8][4];
    #pragma unroll
    for (int i = 0; i < 8; i++)
        #pragma unroll
        for (int j = 0; j < 4; j++) acc[i][j] = 0.f;

    auto fill1 = [&](int buf, int k0) {
        char* base = smem + buf * S1_STRIDE;
        // x tile: 128 n x 64 k fp32 -> fp16 hi only. 2048 f4, 8/thread.
        #pragma unroll
        for (int t = 0; t < 8; t++) {
            int idx = tid + t * 256;
            int row = idx >> 4, cv = idx & 15;
            float4 v = *(const float4*)(xp + (size_t)row * DIN + k0 + cv * 4);
            __half2 h01 = __floats2half2_rn(v.x, v.y);
            __half2 h23 = __floats2half2_rn(v.z, v.w);
            *(uint2*)(base + SW128(row * 128 + cv * 8)) =
                make_uint2(h2u(h01), h2u(h23));
        }
        // B tiles: 64 r x 64 k fp16 hi/lo (pre-split). 512 u4 each, 2/thread.
        #pragma unroll
        for (int t = 0; t < 2; t++) {
            int idx = tid + t * 256;
            int row = idx >> 3, cv = idx & 7;
            size_t e = (size_t)row * DIN + k0 + cv * 8;
            uint32_t off = SW128(row * 128 + cv * 16);
            *(uint4*)(base + S1_BH + off) = *(const uint4*)(bhp + e);
            *(uint4*)(base + S1_BL + off) = *(const uint4*)(blp + e);
        }
    };

    fill1(0, 0);
    __syncthreads();
    for (int c = 0; c < 64; c++) {
        int cur = c & 1;
        if (c < 63) fill1(cur ^ 1, (c + 1) * 64);
        uint32_t xb = sb + cur * S1_STRIDE;
        #pragma unroll
        for (int kc = 0; kc < 4; kc++) {
            uint32_t ah[4];
            LDSM4(ah[0], ah[1], ah[2], ah[3],
                  xb + SW128((w * 16 + lrow) * 128 + kc * 32 + lkb));
            #pragma unroll
            for (int nb = 0; nb < 4; nb++) {
                uint32_t bh[4], bl[4];
                uint32_t off = SW128((nb * 16 + lrow) * 128 + kc * 32 + lkb);
                LDSM4(bh[0], bh[1], bh[2], bh[3], xb + S1_BH + off);
                LDSM4(bl[0], bl[1], bl[2], bl[3], xb + S1_BL + off);
                MMA(acc[2 * nb],     ah, bh[0], bh[2]);
                MMA(acc[2 * nb],     ah, bl[0], bl[2]);
                MMA(acc[2 * nb + 1], ah, bh[1], bh[3]);
                MMA(acc[2 * nb + 1], ah, bl[1], bl[3]);
            }
        }
        __syncthreads();
    }

    // D-frag -> A-frag: Y * 2^-12 as fp16 (values ~0.02 sigma, normal range)
    uint32_t bxh[4][4];
    #pragma unroll
    for (int kc = 0; kc < 4; kc++) {
        #pragma unroll
        for (int h = 0; h < 2; h++) {
            float* d = acc[2 * kc + h];
            const float s = 1.0f / 4096.0f;
            bxh[kc][2 * h]     = h2u(__floats2half2_rn(d[0] * s, d[1] * s));
            bxh[kc][2 * h + 1] = h2u(__floats2half2_rn(d[2] * s, d[3] * s));
        }
    }

    // ======================= STAGE 2 ========================================
    const unsigned short* ahp = g_Ah + (size_t)b * DOUT * RANK;
    const unsigned short* alp = g_Al + (size_t)b * DOUT * RANK;
    float* bp = (float*)(smem + S_BOUNCE) + w * 16 * 68;
    const int r0 = lane >> 2;
    const int c0 = 2 * (lane & 3);

    auto fill2 = [&](int buf, int ot) {
        char* base = smem + buf * S2_STRIDE;
        size_t obase = (size_t)ot * 64 * RANK;
        #pragma unroll
        for (int t = 0; t < 2; t++) {
            int idx = tid + t * 256;
            int row = idx >> 3, cv = idx & 7;
            size_t e = obase + (size_t)row * RANK + cv * 8;
            uint32_t off = SW128(row * 128 + cv * 16);
            *(uint4*)(base + off) = *(const uint4*)(ahp + e);
            *(uint4*)(base + S2_AL + off) = *(const uint4*)(alp + e);
        }
    };

    __syncthreads();
    fill2(0, 0);
    __syncthreads();
    for (int ot = 0; ot < 64; ot++) {
        int cur = ot & 1;
        if (ot < 63) fill2(cur ^ 1, ot + 1);
        uint32_t ab = sb + cur * S2_STRIDE;
        #pragma unroll
        for (int nb = 0; nb < 4; nb++) {       // o-blocks of 16
            float d2[2][4];
            #pragma unroll
            for (int h = 0; h < 2; h++)
                #pragma unroll
                for (int j = 0; j < 4; j++) d2[h][j] = 0.f;
            #pragma unroll
            for (int kc = 0; kc < 4; kc++) {
                uint32_t Ah[4], Al[4];
                uint32_t off = SW128((nb * 16 + lrow) * 128 + kc * 32 + lkb);
                LDSM4(Ah[0], Ah[1], Ah[2], Ah[3], ab + off);
                LDSM4(Al[0], Al[1], Al[2], Al[3], ab + S2_AL + off);
                MMA(d2[0], bxh[kc], Ah[0], Ah[2]);
                MMA(d2[0], bxh[kc], Al[0], Al[2]);
                MMA(d2[1], bxh[kc], Ah[1], Ah[3]);
                MMA(d2[1], bxh[kc], Al[1], Al[3]);
            }
            // residual scaling: (64B)(2^-12)(64A) = B*A exactly; apply 1/64
            *(float2*)(bp + r0 * 68 + nb * 16 + c0) =
                make_float2(d2[0][0] * SCALING, d2[0][1] * SCALING);
            *(float2*)(bp + (r0 + 8) * 68 + nb * 16 + c0) =
                make_float2(d2[0][2] * SCALING, d2[0][3] * SCALING);
            *(float2*)(bp + r0 * 68 + nb * 16 + 8 + c0) =
                make_float2(d2[1][0] * SCALING, d2[1][1] * SCALING);
            *(float2*)(bp + (r0 + 8) * 68 + nb * 16 + 8 + c0) =
                make_float2(d2[1][2] * SCALING, d2[1][3] * SCALING);
        }
        __syncwarp();
        #pragma unroll
        for (int j = 0; j < 8; j++) {
            int row = j * 2 + (lane >> 4);
            int c4 = lane & 15;
            float4 v = *(const float4*)(bp + row * 68 + c4 * 4);
            *(float4*)(out + ((size_t)b * SEQ + (size_t)nt * 128 + w * 16 + row) * DOUT
                           + ot * 64 + c4 * 4) = v;
        }
        __syncthreads();
    }
}

// ---------------------------------------------------------------------------
extern "C" void kernel_launch(void* const* d_in, const int* in_sizes, int n_in,
                              void* d_out, int out_size) {
    const float* x   = (const float*)d_in[0];
    const int*   ids = (const int*)  d_in[1];
    const float* A   = (const float*)d_in[2];
    const float* B   = (const float*)d_in[3];
    float* out = (float*)d_out;

    cudaFuncSetAttribute(fused_kernel, cudaFuncAttributeMaxDynamicSharedMemorySize,
                         SMEM_TOTAL);

    norm_ids_kernel<<<1, 32>>>(ids);

    dim3 gS(256, BATCH, 2);
    split_kernel<<<gS, 256>>>(A, B);

    dim3 gF(SEQ / 128, BATCH);
    fused_kernel<<<gF, 256, SMEM_TOTAL>>>(x, out);

    (void)in_sizes; (void)n_in; (void)out_size;
}

// round 6
// speedup vs baseline: 3.1156x; 1.2476x over previous
#include <cuda_runtime.h>
#include <cuda_fp16.h>
#include <cstdint>

#define BATCH 16
#define SEQ   2048
#define DIN   4096
#define DOUT  4096
#define RANK  64
#define SCALING (1.0f/64.0f)

// ---------------- device scratch (no allocations allowed) -------------------
__device__ unsigned short g_Bh[(size_t)BATCH * RANK * DIN];   // B fp16 [b][r][k]
__device__ unsigned short g_Ah[(size_t)BATCH * DOUT * RANK];  // A fp16 [b][o][r]

// ---------------- helpers ----------------------------------------------------
__device__ __forceinline__ uint32_t smem_u32(const void* p) {
    uint32_t a;
    asm("{ .reg .u64 t; cvta.to.shared.u64 t, %1; cvt.u32.u64 %0, t; }"
        : "=r"(a) : "l"(p));
    return a;
}
#define SW128(o) ((uint32_t)(o) ^ ((((uint32_t)(o)) >> 3) & 0x70))

__device__ __forceinline__ uint32_t h2u(__half2 h) {
    return *reinterpret_cast<uint32_t*>(&h);
}

// ldmatrix x4 (portable PTX, sm_75+)
#define LDSM4(r0, r1, r2, r3, addr) \
    asm volatile("ldmatrix.sync.aligned.m8n8.x4.shared.b16 {%0,%1,%2,%3}, [%4];" \
        : "=r"(r0), "=r"(r1), "=r"(r2), "=r"(r3) : "r"(addr))

// mma.sync fp16, fp32 accumulate (portable PTX, sm_80+)
#define MMA(d, a, b0v, b1v) \
    asm volatile("mma.sync.aligned.m16n8k16.row.col.f32.f16.f16.f32 " \
        "{%0,%1,%2,%3}, {%4,%5,%6,%7}, {%8,%9}, {%0,%1,%2,%3};" \
        : "+f"((d)[0]), "+f"((d)[1]), "+f"((d)[2]), "+f"((d)[3]) \
        : "r"((a)[0]), "r"((a)[1]), "r"((a)[2]), "r"((a)[3]), "r"(b0v), "r"(b1v))

// ---------------------------------------------------------------------------
// adapter id resolution, inlined (handles int64 or int32 adapter_ids buffer):
// int64-LE viewed as int32 has all odd words == 0 (ids < 64); prob of false
// positive on genuine int32 data ~ (1/2^32)^8. Reads only first 64 bytes.
// ---------------------------------------------------------------------------
__device__ __forceinline__ int resolve_id(const int* raw, int b) {
    bool odd_zero = true;
    #pragma unroll
    for (int i = 1; i < 16; i += 2) odd_zero &= (raw[i] == 0);
    return odd_zero ? raw[2 * b] : raw[b];
}

// ---------------------------------------------------------------------------
// Convert requested A/B adapter slices to fp16 (contiguous per-batch blocks).
// grid (128, BATCH, 2), block 256. z=0: B, z=1: A.
// ---------------------------------------------------------------------------
__global__ __launch_bounds__(256) void split_kernel(const float* __restrict__ Am,
                                                    const float* __restrict__ Bm,
                                                    const int* __restrict__ ids) {
    const int b = blockIdx.y;
    const int aid = resolve_id(ids, b);
    const int which = blockIdx.z;
    const size_t i8 = (size_t)blockIdx.x * 256 + threadIdx.x;   // 8-elem index
    const size_t PER = (size_t)RANK * DIN;                      // 262144
    const float* src = (which ? Am : Bm) + (size_t)aid * PER + i8 * 8;
    unsigned short* dh = (which ? g_Ah : g_Bh) + (size_t)b * PER + i8 * 8;
    float4 v0 = *(const float4*)src;
    float4 v1 = *(const float4*)(src + 4);
    *(uint4*)dh = make_uint4(
        h2u(__floats2half2_rn(v0.x, v0.y)), h2u(__floats2half2_rn(v0.z, v0.w)),
        h2u(__floats2half2_rn(v1.x, v1.y)), h2u(__floats2half2_rn(v1.z, v1.w)));
}

// ---------------------------------------------------------------------------
// Fused LoRA kernel (single-term fp16).
// CTA = (128-n tile, batch). 8 warps, warp owns 16 n-rows.
// Stage 1: Y[16x64] = fp16(x) @ fp16(B)^T   (K=4096, fp32 accum)
// Stage 2: out = fp16(Y) @ fp16(A)^T * (1/64)
// smem (51200 B), double-buffered:
//   stage1 buffer stride 24576: XH @+0 (16K), BH @+16384 (8K)
//   stage2 buffer stride 8192:  AH @+0 (8K)
//   bounce @16384 (8 * 16 * 68 * 4 = 34816)
// ---------------------------------------------------------------------------
#define S1_STRIDE 24576
#define S1_BH 16384
#define S2_STRIDE 8192
#define S_BOUNCE 16384
#define SMEM_TOTAL 51200

__global__ __launch_bounds__(256, 2) void fused_kernel(const float* __restrict__ x,
                                                       float* __restrict__ out) {
    extern __shared__ char smem[];
    const uint32_t sb = smem_u32(smem);
    const int tid = threadIdx.x;
    const int w = tid >> 5;
    const int lane = tid & 31;
    const int nt = blockIdx.x;
    const int b = blockIdx.y;

    const float* xp = x + ((size_t)b * SEQ + (size_t)nt * 128) * DIN;
    const unsigned short* bhp = g_Bh + (size_t)b * RANK * DIN;

    const int lrow = lane & 15;
    const int lkb = (lane >> 4) * 16;

    // ======================= STAGE 1 ========================================
    float acc[8][4];
    #pragma unroll
    for (int i = 0; i < 8; i++)
        #pragma unroll
        for (int j = 0; j < 4; j++) acc[i][j] = 0.f;

    auto fill1 = [&](int buf, int k0) {
        char* base = smem + buf * S1_STRIDE;
        // x tile: 128 n x 64 k fp32 -> fp16. 2048 f4, 8/thread.
        #pragma unroll
        for (int t = 0; t < 8; t++) {
            int idx = tid + t * 256;
            int row = idx >> 4, cv = idx & 15;
            float4 v = *(const float4*)(xp + (size_t)row * DIN + k0 + cv * 4);
            *(uint2*)(base + SW128(row * 128 + cv * 8)) = make_uint2(
                h2u(__floats2half2_rn(v.x, v.y)), h2u(__floats2half2_rn(v.z, v.w)));
        }
        // B tile: 64 r x 64 k fp16. 512 u4, 2/thread.
        #pragma unroll
        for (int t = 0; t < 2; t++) {
            int idx = tid + t * 256;
            int row = idx >> 3, cv = idx & 7;
            *(uint4*)(base + S1_BH + SW128(row * 128 + cv * 16)) =
                *(const uint4*)(bhp + (size_t)row * DIN + k0 + cv * 8);
        }
    };

    fill1(0, 0);
    __syncthreads();
    for (int c = 0; c < 64; c++) {
        int cur = c & 1;
        if (c < 63) fill1(cur ^ 1, (c + 1) * 64);
        uint32_t xb = sb + cur * S1_STRIDE;
        #pragma unroll
        for (int kc = 0; kc < 4; kc++) {
            uint32_t ah[4];
            LDSM4(ah[0], ah[1], ah[2], ah[3],
                  xb + SW128((w * 16 + lrow) * 128 + kc * 32 + lkb));
            #pragma unroll
            for (int nb = 0; nb < 4; nb++) {
                uint32_t bh[4];
                LDSM4(bh[0], bh[1], bh[2], bh[3],
                      xb + S1_BH + SW128((nb * 16 + lrow) * 128 + kc * 32 + lkb));
                MMA(acc[2 * nb],     ah, bh[0], bh[2]);
                MMA(acc[2 * nb + 1], ah, bh[1], bh[3]);
            }
        }
        __syncthreads();
    }

    // D-frag -> A-frag for stage 2 (values ~N(0,1.3): fp16-safe directly)
    uint32_t bxh[4][4];
    #pragma unroll
    for (int kc = 0; kc < 4; kc++) {
        #pragma unroll
        for (int h = 0; h < 2; h++) {
            float* d = acc[2 * kc + h];
            bxh[kc][2 * h]     = h2u(__floats2half2_rn(d[0], d[1]));
            bxh[kc][2 * h + 1] = h2u(__floats2half2_rn(d[2], d[3]));
        }
    }

    // ======================= STAGE 2 ========================================
    const unsigned short* ahp = g_Ah + (size_t)b * DOUT * RANK;
    float* bp = (float*)(smem + S_BOUNCE) + w * 16 * 68;
    const int r0 = lane >> 2;
    const int c0 = 2 * (lane & 3);

    auto fill2 = [&](int buf, int ot) {
        char* base = smem + buf * S2_STRIDE;
        size_t obase = (size_t)ot * 64 * RANK;
        #pragma unroll
        for (int t = 0; t < 2; t++) {
            int idx = tid + t * 256;
            int row = idx >> 3, cv = idx & 7;
            *(uint4*)(base + SW128(row * 128 + cv * 16)) =
                *(const uint4*)(ahp + obase + (size_t)row * RANK + cv * 8);
        }
    };

    __syncthreads();
    fill2(0, 0);
    __syncthreads();
    for (int ot = 0; ot < 64; ot++) {
        int cur = ot & 1;
        if (ot < 63) fill2(cur ^ 1, ot + 1);
        uint32_t ab = sb + cur * S2_STRIDE;
        #pragma unroll
        for (int nb = 0; nb < 4; nb++) {       // o-blocks of 16
            float d2[2][4];
            #pragma unroll
            for (int h = 0; h < 2; h++)
                #pragma unroll
                for (int j = 0; j < 4; j++) d2[h][j] = 0.f;
            #pragma unroll
            for (int kc = 0; kc < 4; kc++) {
                uint32_t Ah[4];
                LDSM4(Ah[0], Ah[1], Ah[2], Ah[3],
                      ab + SW128((nb * 16 + lrow) * 128 + kc * 32 + lkb));
                MMA(d2[0], bxh[kc], Ah[0], Ah[2]);
                MMA(d2[1], bxh[kc], Ah[1], Ah[3]);
            }
            *(float2*)(bp + r0 * 68 + nb * 16 + c0) =
                make_float2(d2[0][0] * SCALING, d2[0][1] * SCALING);
            *(float2*)(bp + (r0 + 8) * 68 + nb * 16 + c0) =
                make_float2(d2[0][2] * SCALING, d2[0][3] * SCALING);
            *(float2*)(bp + r0 * 68 + nb * 16 + 8 + c0) =
                make_float2(d2[1][0] * SCALING, d2[1][1] * SCALING);
            *(float2*)(bp + (r0 + 8) * 68 + nb * 16 + 8 + c0) =
                make_float2(d2[1][2] * SCALING, d2[1][3] * SCALING);
        }
        __syncwarp();
        // coalesced stores: 16 rows x 64 floats, 256B segments per row
        #pragma unroll
        for (int j = 0; j < 8; j++) {
            int row = j * 2 + (lane >> 4);
            int c4 = lane & 15;
            float4 v = *(const float4*)(bp + row * 68 + c4 * 4);
            *(float4*)(out + ((size_t)b * SEQ + (size_t)nt * 128 + w * 16 + row) * DOUT
                           + ot * 64 + c4 * 4) = v;
        }
        __syncthreads();
    }
}

// ---------------------------------------------------------------------------
extern "C" void kernel_launch(void* const* d_in, const int* in_sizes, int n_in,
                              void* d_out, int out_size) {
    const float* x   = (const float*)d_in[0];
    const int*   ids = (const int*)  d_in[1];
    const float* A   = (const float*)d_in[2];
    const float* B   = (const float*)d_in[3];
    float* out = (float*)d_out;

    cudaFuncSetAttribute(fused_kernel, cudaFuncAttributeMaxDynamicSharedMemorySize,
                         SMEM_TOTAL);

    dim3 gS(128, BATCH, 2);
    split_kernel<<<gS, 256>>>(A, B, ids);

    dim3 gF(SEQ / 128, BATCH);
    fused_kernel<<<gF, 256, SMEM_TOTAL>>>(x, out);

    (void)in_sizes; (void)n_in; (void)out_size;
}

// round 7
// speedup vs baseline: 3.5333x; 1.1341x over previous
#include <cuda_runtime.h>
#include <cuda_fp16.h>
#include <cstdint>

#define BATCH 16
#define SEQ   2048
#define DIN   4096
#define DOUT  4096
#define RANK  64
#define SCALING (1.0f/64.0f)

// ---------------- device scratch (no allocations allowed) -------------------
__device__ unsigned short g_Bh[(size_t)BATCH * RANK * DIN];   // B fp16 [b][r][k]
__device__ unsigned short g_Ah[(size_t)BATCH * DOUT * RANK];  // A fp16 [b][o][r]

// ---------------- helpers ----------------------------------------------------
__device__ __forceinline__ uint32_t smem_u32(const void* p) {
    uint32_t a;
    asm("{ .reg .u64 t; cvta.to.shared.u64 t, %1; cvt.u32.u64 %0, t; }"
        : "=r"(a) : "l"(p));
    return a;
}
#define SW64(o)  ((uint32_t)(o) ^ ((((uint32_t)(o)) >> 3) & 0x30))
#define SW128(o) ((uint32_t)(o) ^ ((((uint32_t)(o)) >> 3) & 0x70))

__device__ __forceinline__ uint32_t h2u(__half2 h) {
    return *reinterpret_cast<uint32_t*>(&h);
}

// cp.async (portable PTX, sm_80+)
#define CP_ASYNC16(dst, src) \
    asm volatile("cp.async.cg.shared.global [%0], [%1], 16;" :: "r"(dst), "l"(src))
#define CP_COMMIT() asm volatile("cp.async.commit_group;" ::: "memory")
#define CP_WAIT2()  asm volatile("cp.async.wait_group 2;" ::: "memory")

// ldmatrix x4 (portable PTX, sm_75+)
#define LDSM4(r0, r1, r2, r3, addr) \
    asm volatile("ldmatrix.sync.aligned.m8n8.x4.shared.b16 {%0,%1,%2,%3}, [%4];" \
        : "=r"(r0), "=r"(r1), "=r"(r2), "=r"(r3) : "r"(addr))

// mma.sync fp16, fp32 accumulate (portable PTX, sm_80+)
#define MMA(d, a, b0v, b1v) \
    asm volatile("mma.sync.aligned.m16n8k16.row.col.f32.f16.f16.f32 " \
        "{%0,%1,%2,%3}, {%4,%5,%6,%7}, {%8,%9}, {%0,%1,%2,%3};" \
        : "+f"((d)[0]), "+f"((d)[1]), "+f"((d)[2]), "+f"((d)[3]) \
        : "r"((a)[0]), "r"((a)[1]), "r"((a)[2]), "r"((a)[3]), "r"(b0v), "r"(b1v))

// ---------------------------------------------------------------------------
// adapter id resolution (int64 or int32 buffer; reads first 64 bytes only)
// ---------------------------------------------------------------------------
__device__ __forceinline__ int resolve_id(const int* raw, int b) {
    bool odd_zero = true;
    #pragma unroll
    for (int i = 1; i < 16; i += 2) odd_zero &= (raw[i] == 0);
    return odd_zero ? raw[2 * b] : raw[b];
}

// ---------------------------------------------------------------------------
// Convert requested A/B adapter slices to fp16.
// grid (128, BATCH, 2), block 256. z=0: B, z=1: A.
// ---------------------------------------------------------------------------
__global__ __launch_bounds__(256) void split_kernel(const float* __restrict__ Am,
                                                    const float* __restrict__ Bm,
                                                    const int* __restrict__ ids) {
    const int b = blockIdx.y;
    const int aid = resolve_id(ids, b);
    const int which = blockIdx.z;
    const size_t i8 = (size_t)blockIdx.x * 256 + threadIdx.x;
    const size_t PER = (size_t)RANK * DIN;
    const float* src = (which ? Am : Bm) + (size_t)aid * PER + i8 * 8;
    unsigned short* dh = (which ? g_Ah : g_Bh) + (size_t)b * PER + i8 * 8;
    float4 v0 = *(const float4*)src;
    float4 v1 = *(const float4*)(src + 4);
    *(uint4*)dh = make_uint4(
        h2u(__floats2half2_rn(v0.x, v0.y)), h2u(__floats2half2_rn(v0.z, v0.w)),
        h2u(__floats2half2_rn(v1.x, v1.y)), h2u(__floats2half2_rn(v1.z, v1.w)));
}

// ---------------------------------------------------------------------------
// Fused LoRA kernel (single-term fp16, cp.async 4-deep pipelines).
// CTA = (128-n tile, batch). 8 warps, warp owns 16 n-rows.
// Stage 1: Y[16x64] = fp16(x) @ fp16(B)^T   (K=4096 in 128 chunks of 32)
//   x: cp.async fp32 tiles -> LDS.64 + cvt directly into MMA a-frags.
//   B: cp.async fp16 swizzled tiles -> ldmatrix.
// Stage 2: out = fp16(Y) @ fp16(A)^T * (1/64), 64 o-tiles of 64.
// smem layout (90112 B total):
//   stage1: 4 x-bufs [128][36] fp32 @0 (4*18432), 4 B-bufs @73728 (4*4096)
//   stage2: 4 A-bufs @0 (4*8192), bounce @32768 (34816)
// ---------------------------------------------------------------------------
#define CK 32
#define NCH (DIN / CK)          // 128
#define XS 36                   // fp32 row stride (144B, 16B-aligned)
#define XBUF_SZ (128 * XS * 4)  // 18432
#define BBUF_SZ (64 * CK * 2)   // 4096
#define S_B 73728
#define S2_BOUNCE 32768
#define SMEM_TOTAL 90112

__global__ __launch_bounds__(256, 2) void fused_kernel(const float* __restrict__ x,
                                                       float* __restrict__ out) {
    extern __shared__ char smem[];
    const uint32_t sb = smem_u32(smem);
    const int tid = threadIdx.x;
    const int w = tid >> 5;
    const int lane = tid & 31;
    const int nt = blockIdx.x;
    const int b = blockIdx.y;

    const float* xp = x + ((size_t)b * SEQ + (size_t)nt * 128) * DIN;
    const unsigned short* bhp = g_Bh + (size_t)b * RANK * DIN;
    const unsigned short* ahp = g_Ah + (size_t)b * DOUT * RANK;

    const int lrow = lane & 15;
    const int lkb = (lane >> 4) * 16;

    // ======================= STAGE 1 ========================================
    float acc[8][4];
    #pragma unroll
    for (int i = 0; i < 8; i++)
        #pragma unroll
        for (int j = 0; j < 4; j++) acc[i][j] = 0.f;

    auto issue1 = [&](int ch) {
        if (ch < NCH) {
            const int buf = ch & 3;
            const int k0 = ch * CK;
            // x: 128 rows x 32 fp32 = 1024 x 16B, 4 per thread
            #pragma unroll
            for (int t = 0; t < 4; t++) {
                int idx = tid + t * 256;
                int row = idx >> 3, f4 = idx & 7;
                CP_ASYNC16(sb + buf * XBUF_SZ + row * 144 + f4 * 16,
                           xp + (size_t)row * DIN + k0 + f4 * 4);
            }
            // B: 64 rows x 32 fp16 = 256 x 16B, 1 per thread
            {
                int row = tid >> 2, f4 = tid & 3;
                CP_ASYNC16(sb + S_B + buf * BBUF_SZ + SW64(row * 64 + f4 * 16),
                           bhp + (size_t)row * DIN + k0 + f4 * 8);
            }
        }
        CP_COMMIT();
    };

    issue1(0);
    issue1(1);
    const int xr = w * 16 + (lane >> 2);       // a-frag row
    const int xc = (lane & 3) * 2;             // a-frag col base
    for (int c = 0; c < NCH; c++) {
        issue1(c + 2);
        CP_WAIT2();
        __syncthreads();
        const float* xb = (const float*)(smem + (c & 3) * XBUF_SZ);
        const uint32_t bbase = sb + S_B + (c & 3) * BBUF_SZ;
        #pragma unroll
        for (int kc = 0; kc < 2; kc++) {
            // build a-frag from fp32 smem: a0(r,c) a1(r+8,c) a2(r,c+8) a3(r+8,c+8)
            const int cb = kc * 16 + xc;
            float2 f0 = *(const float2*)(xb + xr * XS + cb);
            float2 f1 = *(const float2*)(xb + (xr + 8) * XS + cb);
            float2 f2 = *(const float2*)(xb + xr * XS + cb + 8);
            float2 f3 = *(const float2*)(xb + (xr + 8) * XS + cb + 8);
            uint32_t a[4] = {
                h2u(__floats2half2_rn(f0.x, f0.y)), h2u(__floats2half2_rn(f1.x, f1.y)),
                h2u(__floats2half2_rn(f2.x, f2.y)), h2u(__floats2half2_rn(f3.x, f3.y))};
            #pragma unroll
            for (int nb = 0; nb < 4; nb++) {
                uint32_t bh[4];
                LDSM4(bh[0], bh[1], bh[2], bh[3],
                      bbase + SW64((nb * 16 + lrow) * 64 + kc * 32 + lkb));
                MMA(acc[2 * nb],     a, bh[0], bh[2]);
                MMA(acc[2 * nb + 1], a, bh[1], bh[3]);
            }
        }
    }

    // D-frag -> stage2 A-frag (fp16)
    uint32_t bxh[4][4];
    #pragma unroll
    for (int kc = 0; kc < 4; kc++) {
        #pragma unroll
        for (int h = 0; h < 2; h++) {
            float* d = acc[2 * kc + h];
            bxh[kc][2 * h]     = h2u(__floats2half2_rn(d[0], d[1]));
            bxh[kc][2 * h + 1] = h2u(__floats2half2_rn(d[2], d[3]));
        }
    }
    __syncthreads();   // stage1 smem reads complete before stage2 overwrites

    // ======================= STAGE 2 ========================================
    float* bp = (float*)(smem + S2_BOUNCE) + w * 16 * 68;
    const int r0 = lane >> 2;
    const int c0 = 2 * (lane & 3);

    auto issue2 = [&](int ot) {
        if (ot < 64) {
            const int buf = ot & 3;
            // A tile: 64 o x 64 r fp16 = 512 x 16B, 2 per thread
            #pragma unroll
            for (int t = 0; t < 2; t++) {
                int idx = tid + t * 256;
                int row = idx >> 3, f4 = idx & 7;
                CP_ASYNC16(sb + buf * 8192 + SW128(row * 128 + f4 * 16),
                           ahp + (size_t)(ot * 64 + row) * RANK + f4 * 8);
            }
        }
        CP_COMMIT();
    };

    issue2(0);
    issue2(1);
    for (int ot = 0; ot < 64; ot++) {
        issue2(ot + 2);
        CP_WAIT2();
        __syncthreads();
        const uint32_t ab = sb + (ot & 3) * 8192;
        #pragma unroll
        for (int nb = 0; nb < 4; nb++) {       // o-blocks of 16
            float d2[2][4];
            #pragma unroll
            for (int h = 0; h < 2; h++)
                #pragma unroll
                for (int j = 0; j < 4; j++) d2[h][j] = 0.f;
            #pragma unroll
            for (int kc = 0; kc < 4; kc++) {
                uint32_t Ah[4];
                LDSM4(Ah[0], Ah[1], Ah[2], Ah[3],
                      ab + SW128((nb * 16 + lrow) * 128 + kc * 32 + lkb));
                MMA(d2[0], bxh[kc], Ah[0], Ah[2]);
                MMA(d2[1], bxh[kc], Ah[1], Ah[3]);
            }
            *(float2*)(bp + r0 * 68 + nb * 16 + c0) =
                make_float2(d2[0][0] * SCALING, d2[0][1] * SCALING);
            *(float2*)(bp + (r0 + 8) * 68 + nb * 16 + c0) =
                make_float2(d2[0][2] * SCALING, d2[0][3] * SCALING);
            *(float2*)(bp + r0 * 68 + nb * 16 + 8 + c0) =
                make_float2(d2[1][0] * SCALING, d2[1][1] * SCALING);
            *(float2*)(bp + (r0 + 8) * 68 + nb * 16 + 8 + c0) =
                make_float2(d2[1][2] * SCALING, d2[1][3] * SCALING);
        }
        __syncwarp();
        // coalesced stores: 16 rows x 64 floats (256B per row)
        #pragma unroll
        for (int j = 0; j < 8; j++) {
            int row = j * 2 + (lane >> 4);
            int c4 = lane & 15;
            float4 v = *(const float4*)(bp + row * 68 + c4 * 4);
            *(float4*)(out + ((size_t)b * SEQ + (size_t)nt * 128 + w * 16 + row) * DOUT
                           + ot * 64 + c4 * 4) = v;
        }
    }
}

// ---------------------------------------------------------------------------
extern "C" void kernel_launch(void* const* d_in, const int* in_sizes, int n_in,
                              void* d_out, int out_size) {
    const float* x   = (const float*)d_in[0];
    const int*   ids = (const int*)  d_in[1];
    const float* A   = (const float*)d_in[2];
    const float* B   = (const float*)d_in[3];
    float* out = (float*)d_out;

    cudaFuncSetAttribute(fused_kernel, cudaFuncAttributeMaxDynamicSharedMemorySize,
                         SMEM_TOTAL);

    dim3 gS(128, BATCH, 2);
    split_kernel<<<gS, 256>>>(A, B, ids);

    dim3 gF(SEQ / 128, BATCH);
    fused_kernel<<<gF, 256, SMEM_TOTAL>>>(x, out);

    (void)in_sizes; (void)n_in; (void)out_size;
}

// round 8
// speedup vs baseline: 3.7624x; 1.0648x over previous
#include <cuda_runtime.h>
#include <cuda_fp16.h>
#include <cstdint>

#define BATCH 16
#define SEQ   2048
#define DIN   4096
#define DOUT  4096
#define RANK  64
#define SCALING (1.0f/64.0f)

// ---------------- device scratch (no allocations allowed) -------------------
__device__ unsigned short g_Bh[(size_t)BATCH * RANK * DIN];   // B fp16 [b][r][k]
__device__ unsigned short g_Ah[(size_t)BATCH * DOUT * RANK];  // A fp16 [b][o][r]

// ---------------- helpers ----------------------------------------------------
__device__ __forceinline__ uint32_t smem_u32(const void* p) {
    uint32_t a;
    asm("{ .reg .u64 t; cvta.to.shared.u64 t, %1; cvt.u32.u64 %0, t; }"
        : "=r"(a) : "l"(p));
    return a;
}
#define SW64(o)  ((uint32_t)(o) ^ ((((uint32_t)(o)) >> 3) & 0x30))
#define SW128(o) ((uint32_t)(o) ^ ((((uint32_t)(o)) >> 3) & 0x70))

__device__ __forceinline__ uint32_t h2u(__half2 h) {
    return *reinterpret_cast<uint32_t*>(&h);
}

// cp.async (portable PTX, sm_80+)
#define CP_ASYNC16(dst, src) \
    asm volatile("cp.async.cg.shared.global [%0], [%1], 16;" :: "r"(dst), "l"(src))
#define CP_COMMIT() asm volatile("cp.async.commit_group;" ::: "memory")
#define CP_WAIT1()  asm volatile("cp.async.wait_group 1;" ::: "memory")

// ldmatrix x4 (portable PTX, sm_75+)
#define LDSM4(r0, r1, r2, r3, addr) \
    asm volatile("ldmatrix.sync.aligned.m8n8.x4.shared.b16 {%0,%1,%2,%3}, [%4];" \
        : "=r"(r0), "=r"(r1), "=r"(r2), "=r"(r3) : "r"(addr))

// mma.sync fp16, fp32 accumulate (portable PTX, sm_80+)
#define MMA(d, a, b0v, b1v) \
    asm volatile("mma.sync.aligned.m16n8k16.row.col.f32.f16.f16.f32 " \
        "{%0,%1,%2,%3}, {%4,%5,%6,%7}, {%8,%9}, {%0,%1,%2,%3};" \
        : "+f"((d)[0]), "+f"((d)[1]), "+f"((d)[2]), "+f"((d)[3]) \
        : "r"((a)[0]), "r"((a)[1]), "r"((a)[2]), "r"((a)[3]), "r"(b0v), "r"(b1v))

// ---------------------------------------------------------------------------
// adapter id resolution (int64 or int32 buffer; reads first 64 bytes only)
// ---------------------------------------------------------------------------
__device__ __forceinline__ int resolve_id(const int* raw, int b) {
    bool odd_zero = true;
    #pragma unroll
    for (int i = 1; i < 16; i += 2) odd_zero &= (raw[i] == 0);
    return odd_zero ? raw[2 * b] : raw[b];
}

// ---------------------------------------------------------------------------
// Convert requested A/B adapter slices to fp16.
// grid (128, BATCH, 2), block 256. z=0: B, z=1: A.
// ---------------------------------------------------------------------------
__global__ __launch_bounds__(256) void split_kernel(const float* __restrict__ Am,
                                                    const float* __restrict__ Bm,
                                                    const int* __restrict__ ids) {
    const int b = blockIdx.y;
    const int aid = resolve_id(ids, b);
    const int which = blockIdx.z;
    const size_t i8 = (size_t)blockIdx.x * 256 + threadIdx.x;
    const size_t PER = (size_t)RANK * DIN;
    const float* src = (which ? Am : Bm) + (size_t)aid * PER + i8 * 8;
    unsigned short* dh = (which ? g_Ah : g_Bh) + (size_t)b * PER + i8 * 8;
    float4 v0 = *(const float4*)src;
    float4 v1 = *(const float4*)(src + 4);
    *(uint4*)dh = make_uint4(
        h2u(__floats2half2_rn(v0.x, v0.y)), h2u(__floats2half2_rn(v0.z, v0.w)),
        h2u(__floats2half2_rn(v1.x, v1.y)), h2u(__floats2half2_rn(v1.z, v1.w)));
}

// ---------------------------------------------------------------------------
// Fused LoRA kernel (single-term fp16, cp.async 3-buffer pipelines, 3 CTA/SM).
// CTA = (128-n tile, batch). 8 warps, warp owns 16 n-rows.
// Stage 1: Y[16x64] = fp16(x) @ fp16(B)^T   (K=4096 in 128 chunks of 32)
// Stage 2: out = fp16(Y) @ fp16(A)^T * (1/64), 32 o-tiles of 128,
//          direct STG.64 stores (32B/quad segments -> full sector use).
// smem (73728 B):
//   stage1: 3 x-bufs [128][40] fp32 @0 (3*20480), 3 B-bufs @61440 (3*4096)
//   stage2: 3 A-bufs @0 (3*16384)
// Pipeline order per iter: WAIT -> BARRIER -> ISSUE(c+2) -> COMPUTE(c); with
// 3 buffers this is race-free (issue writes buf (c-1)%3, whose readers
// finished before the barrier).
// ---------------------------------------------------------------------------
#define CK 32
#define NCH (DIN / CK)            // 128
#define XS 40                     // fp32 row stride in words (160B)
#define XBUF_SZ (128 * XS * 4)    // 20480
#define BBUF_SZ (64 * CK * 2)     // 4096
#define S_B 61440
#define ABUF_SZ 16384
#define SMEM_TOTAL 73728

__global__ __launch_bounds__(256, 3) void fused_kernel(const float* __restrict__ x,
                                                       float* __restrict__ out) {
    extern __shared__ char smem[];
    const uint32_t sb = smem_u32(smem);
    const int tid = threadIdx.x;
    const int w = tid >> 5;
    const int lane = tid & 31;
    const int nt = blockIdx.x;
    const int b = blockIdx.y;

    const float* xp = x + ((size_t)b * SEQ + (size_t)nt * 128) * DIN;
    const unsigned short* bhp = g_Bh + (size_t)b * RANK * DIN;
    const unsigned short* ahp = g_Ah + (size_t)b * DOUT * RANK;

    const int lrow = lane & 15;
    const int lkb = (lane >> 4) * 16;

    // ======================= STAGE 1 ========================================
    float acc[8][4];
    #pragma unroll
    for (int i = 0; i < 8; i++)
        #pragma unroll
        for (int j = 0; j < 4; j++) acc[i][j] = 0.f;

    auto issue1 = [&](int ch) {
        if (ch < NCH) {
            const int buf = ch % 3;
            const int k0 = ch * CK;
            // x: 128 rows x 32 fp32 = 1024 x 16B, 4 per thread
            #pragma unroll
            for (int t = 0; t < 4; t++) {
                int idx = tid + t * 256;
                int row = idx >> 3, f4 = idx & 7;
                CP_ASYNC16(sb + buf * XBUF_SZ + row * (XS * 4) + f4 * 16,
                           xp + (size_t)row * DIN + k0 + f4 * 4);
            }
            // B: 64 rows x 32 fp16 = 256 x 16B, 1 per thread
            {
                int row = tid >> 2, f4 = tid & 3;
                CP_ASYNC16(sb + S_B + buf * BBUF_SZ + SW64(row * 64 + f4 * 16),
                           bhp + (size_t)row * DIN + k0 + f4 * 8);
            }
        }
        CP_COMMIT();
    };

    issue1(0);
    issue1(1);
    const int xr = w * 16 + (lane >> 2);       // a-frag row
    const int xc = (lane & 3) * 2;             // a-frag col base
    for (int c = 0; c < NCH; c++) {
        CP_WAIT1();
        __syncthreads();
        issue1(c + 2);
        const float* xb = (const float*)(smem + (c % 3) * XBUF_SZ);
        const uint32_t bbase = sb + S_B + (c % 3) * BBUF_SZ;
        #pragma unroll
        for (int kc = 0; kc < 2; kc++) {
            const int cb = kc * 16 + xc;
            float2 f0 = *(const float2*)(xb + xr * XS + cb);
            float2 f1 = *(const float2*)(xb + (xr + 8) * XS + cb);
            float2 f2 = *(const float2*)(xb + xr * XS + cb + 8);
            float2 f3 = *(const float2*)(xb + (xr + 8) * XS + cb + 8);
            uint32_t a[4] = {
                h2u(__floats2half2_rn(f0.x, f0.y)), h2u(__floats2half2_rn(f1.x, f1.y)),
                h2u(__floats2half2_rn(f2.x, f2.y)), h2u(__floats2half2_rn(f3.x, f3.y))};
            #pragma unroll
            for (int nb = 0; nb < 4; nb++) {
                uint32_t bh[4];
                LDSM4(bh[0], bh[1], bh[2], bh[3],
                      bbase + SW64((nb * 16 + lrow) * 64 + kc * 32 + lkb));
                MMA(acc[2 * nb],     a, bh[0], bh[2]);
                MMA(acc[2 * nb + 1], a, bh[1], bh[3]);
            }
        }
    }

    // D-frag -> stage2 A-frag (fp16)
    uint32_t bxh[4][4];
    #pragma unroll
    for (int kc = 0; kc < 4; kc++) {
        #pragma unroll
        for (int h = 0; h < 2; h++) {
            float* d = acc[2 * kc + h];
            bxh[kc][2 * h]     = h2u(__floats2half2_rn(d[0], d[1]));
            bxh[kc][2 * h + 1] = h2u(__floats2half2_rn(d[2], d[3]));
        }
    }
    __syncthreads();   // all stage1 smem reads done before stage2 overwrites

    // ======================= STAGE 2 ========================================
    const int r0 = lane >> 2;
    const int c0 = 2 * (lane & 3);
    const size_t orow0 = (size_t)b * SEQ + (size_t)nt * 128 + w * 16;

    auto issue2 = [&](int ot) {
        if (ot < 32) {
            const int buf = ot % 3;
            // A tile: 128 o x 64 r fp16 = 1024 x 16B, 4 per thread
            #pragma unroll
            for (int t = 0; t < 4; t++) {
                int idx = tid + t * 256;
                int row = idx >> 3, f4 = idx & 7;
                CP_ASYNC16(sb + buf * ABUF_SZ + SW128(row * 128 + f4 * 16),
                           ahp + (size_t)(ot * 128 + row) * RANK + f4 * 8);
            }
        }
        CP_COMMIT();
    };

    issue2(0);
    issue2(1);
    for (int ot = 0; ot < 32; ot++) {
        CP_WAIT1();
        __syncthreads();
        issue2(ot + 2);
        const uint32_t ab = sb + (ot % 3) * ABUF_SZ;
        #pragma unroll
        for (int nb = 0; nb < 8; nb++) {       // o-blocks of 16
            float d2[2][4];
            #pragma unroll
            for (int h = 0; h < 2; h++)
                #pragma unroll
                for (int j = 0; j < 4; j++) d2[h][j] = 0.f;
            #pragma unroll
            for (int kc = 0; kc < 4; kc++) {
                uint32_t Ah[4];
                LDSM4(Ah[0], Ah[1], Ah[2], Ah[3],
                      ab + SW128((nb * 16 + lrow) * 128 + kc * 32 + lkb));
                MMA(d2[0], bxh[kc], Ah[0], Ah[2]);
                MMA(d2[1], bxh[kc], Ah[1], Ah[3]);
            }
            // direct stores: quad-contiguous 32B segments
            float* o0 = out + (orow0 + r0) * DOUT + ot * 128 + nb * 16 + c0;
            float* o1 = out + (orow0 + r0 + 8) * DOUT + ot * 128 + nb * 16 + c0;
            *(float2*)o0       = make_float2(d2[0][0] * SCALING, d2[0][1] * SCALING);
            *(float2*)o1       = make_float2(d2[0][2] * SCALING, d2[0][3] * SCALING);
            *(float2*)(o0 + 8) = make_float2(d2[1][0] * SCALING, d2[1][1] * SCALING);
            *(float2*)(o1 + 8) = make_float2(d2[1][2] * SCALING, d2[1][3] * SCALING);
        }
    }
}

// ---------------------------------------------------------------------------
extern "C" void kernel_launch(void* const* d_in, const int* in_sizes, int n_in,
                              void* d_out, int out_size) {
    const float* x   = (const float*)d_in[0];
    const int*   ids = (const int*)  d_in[1];
    const float* A   = (const float*)d_in[2];
    const float* B   = (const float*)d_in[3];
    float* out = (float*)d_out;

    cudaFuncSetAttribute(fused_kernel, cudaFuncAttributeMaxDynamicSharedMemorySize,
                         SMEM_TOTAL);

    dim3 gS(128, BATCH, 2);
    split_kernel<<<gS, 256>>>(A, B, ids);

    dim3 gF(SEQ / 128, BATCH);
    fused_kernel<<<gF, 256, SMEM_TOTAL>>>(x, out);

    (void)in_sizes; (void)n_in; (void)out_size;
}